// round 4
// baseline (speedup 1.0000x reference)
#include <cuda_runtime.h>
#include <cuda_bf16.h>
#include <cstdint>

// Problem: out[b,n,e] = sum_m A[n,m] * (sum_d Z[b,m,d] * W[d,e])
// B=16, N=4096, D_IN=64, D_OUT=64
// Strategy:
//   X[m, b*64+e] = Z[b,m,:] @ W[:,e]            (small GEMM, K=64)
//   out(n, c)    = A[n,:] @ X[:, c]             (M=4096, N=1024, K=4096, tf32 mma)
// Both operands of the big GEMM are pre-rounded to tf32 (rna) for accuracy.

#define NROWS 4096
#define NCOLS 1024      // 16 batches * 64 out-features
#define KDIM  4096

// ---------------- scratch (static device globals; no allocation) ----------------
__device__ __align__(256) float g_Atf[NROWS * KDIM];   // tf32-rounded A  (64 MB)
__device__ __align__(256) float g_X[KDIM * NCOLS];     // tf32-rounded Z@W (16 MB)

// ---------------- helpers ----------------
__device__ __forceinline__ float tf32_round(float x) {
    uint32_t u;
    asm volatile("cvt.rna.tf32.f32 %0, %1;\n" : "=r"(u) : "f"(x));
    return __uint_as_float(u);
}

__device__ __forceinline__ void cp_async16(void* dst_smem, const void* src_gmem) {
    unsigned s = (unsigned)__cvta_generic_to_shared(dst_smem);
    asm volatile("cp.async.cg.shared.global [%0], [%1], 16;\n" :: "r"(s), "l"(src_gmem));
}
__device__ __forceinline__ void cp_commit() {
    asm volatile("cp.async.commit_group;\n");
}

// ---------------- kernel 0: round A to tf32 ----------------
__global__ void __launch_bounds__(256) convA_kernel(const float4* __restrict__ A) {
    int i = blockIdx.x * 256 + threadIdx.x;   // 16384 blocks * 256 = 4,194,304 float4
    float4 v = __ldg(A + i);
    float4 o;
    o.x = tf32_round(v.x);
    o.y = tf32_round(v.y);
    o.z = tf32_round(v.z);
    o.w = tf32_round(v.w);
    reinterpret_cast<float4*>(g_Atf)[i] = o;
}

// ---------------- kernel 1: X = Z @ W (per batch), tf32-rounded ----------------
// X[m*1024 + b*64 + e] = sum_d Z[(b*4096+m)*64 + d] * W[d*64 + e]
__global__ void __launch_bounds__(256) gemm1_kernel(const float* __restrict__ Z,
                                                    const float* __restrict__ W) {
    __shared__ float Ws[64 * 64];
    const int tid = threadIdx.x;
    // stage W into smem (1024 float4 by 256 threads)
    #pragma unroll
    for (int r = 0; r < 4; r++) {
        int i = tid + r * 256;
        reinterpret_cast<float4*>(Ws)[i] =
            __ldg(reinterpret_cast<const float4*>(W) + i);
    }
    __syncthreads();

    const int p  = blockIdx.x * 32 + (tid >> 3);   // (m,b) pair index, 65536 total
    const int e0 = (tid & 7) * 8;
    const int m  = p >> 4;
    const int b  = p & 15;

    const float* zr = Z + ((size_t)((b << 12) + m)) * 64;
    float z[64];
    #pragma unroll
    for (int i = 0; i < 16; i++)
        reinterpret_cast<float4*>(z)[i] = __ldg(reinterpret_cast<const float4*>(zr) + i);

    float acc[8];
    #pragma unroll
    for (int j = 0; j < 8; j++) acc[j] = 0.0f;

    #pragma unroll
    for (int d = 0; d < 64; d++) {
        float4 w0 = *reinterpret_cast<const float4*>(Ws + d * 64 + e0);
        float4 w1 = *reinterpret_cast<const float4*>(Ws + d * 64 + e0 + 4);
        float zv = z[d];
        acc[0] = fmaf(zv, w0.x, acc[0]);
        acc[1] = fmaf(zv, w0.y, acc[1]);
        acc[2] = fmaf(zv, w0.z, acc[2]);
        acc[3] = fmaf(zv, w0.w, acc[3]);
        acc[4] = fmaf(zv, w1.x, acc[4]);
        acc[5] = fmaf(zv, w1.y, acc[5]);
        acc[6] = fmaf(zv, w1.z, acc[6]);
        acc[7] = fmaf(zv, w1.w, acc[7]);
    }

    float* xp = g_X + (size_t)m * NCOLS + b * 64 + e0;
    float4 o0, o1;
    o0.x = tf32_round(acc[0]); o0.y = tf32_round(acc[1]);
    o0.z = tf32_round(acc[2]); o0.w = tf32_round(acc[3]);
    o1.x = tf32_round(acc[4]); o1.y = tf32_round(acc[5]);
    o1.z = tf32_round(acc[6]); o1.w = tf32_round(acc[7]);
    *reinterpret_cast<float4*>(xp)     = o0;
    *reinterpret_cast<float4*>(xp + 4) = o1;
}

// ---------------- kernel 2: out = A_tf @ X  (tf32 mma, 3-stage cp.async) ----------------
#define BM 128
#define BN 128
#define BK 32
#define STAGES 3
#define LDA_S 36    // BK + 4  -> conflict-free A fragment LDS
#define LDB_S 136   // BN + 8  -> conflict-free B fragment LDS
#define KT (KDIM / BK)   // 128 k-tiles
#define SMEM_FLOATS (STAGES * BM * LDA_S + STAGES * BK * LDB_S)   // 26880
#define SMEM_BYTES  (SMEM_FLOATS * 4)                              // 107520

__global__ void __launch_bounds__(256, 2) gemm2_kernel(float* __restrict__ out) {
    extern __shared__ float smem[];
    float* As = smem;                                // [STAGES][BM][LDA_S]
    float* Bs = smem + STAGES * BM * LDA_S;          // [STAGES][BK][LDB_S]

    const int tid  = threadIdx.x;
    const int wid  = tid >> 5;
    const int lane = tid & 31;
    const int g    = lane >> 2;    // 0..7
    const int t4   = lane & 3;     // 0..3
    const int wm   = (wid & 1) * 64;    // warp m-offset (2 warps along M)
    const int wn   = (wid >> 1) * 32;   // warp n-offset (4 warps along N)
    const int bm   = blockIdx.y;        // 0..31
    const int bn   = blockIdx.x;        // 0..7

    const float* Ag0 = g_Atf + (size_t)(bm * BM) * KDIM;
    const float* Bg0 = g_X;

    // ---- async tile loader ----
    auto load_tile = [&](int kt, int s) {
        const float* Ag = Ag0 + kt * BK;
        float* Asd = As + s * BM * LDA_S;
        #pragma unroll
        for (int r = 0; r < 4; r++) {
            int i   = tid + r * 256;      // 1024 float4 for A tile
            int row = i >> 3;             // 8 float4 per 32-float row
            int cv  = (i & 7) * 4;
            cp_async16(Asd + row * LDA_S + cv, Ag + (size_t)row * KDIM + cv);
        }
        const float* Bg = Bg0 + (size_t)(kt * BK) * NCOLS + bn * BN;
        float* Bsd = Bs + s * BK * LDB_S;
        #pragma unroll
        for (int r = 0; r < 4; r++) {
            int i   = tid + r * 256;      // 1024 float4 for B tile
            int row = i >> 5;             // 32 float4 per 128-float row
            int cv  = (i & 31) * 4;
            cp_async16(Bsd + row * LDB_S + cv, Bg + (size_t)row * NCOLS + cv);
        }
    };

    float acc[4][4][4];
    #pragma unroll
    for (int a = 0; a < 4; a++)
        #pragma unroll
        for (int b = 0; b < 4; b++)
            #pragma unroll
            for (int c = 0; c < 4; c++) acc[a][b][c] = 0.0f;

    // prologue: 2 tiles in flight
    load_tile(0, 0); cp_commit();
    load_tile(1, 1); cp_commit();

    for (int kt = 0; kt < KT; kt++) {
        int lt = kt + 2;
        if (lt < KT) load_tile(lt, lt % STAGES);
        cp_commit();                                   // (possibly empty) group
        asm volatile("cp.async.wait_group 1;\n");      // tile kt guaranteed done
        __syncthreads();

        const float* Asc = As + (kt % STAGES) * BM * LDA_S;
        const float* Bsc = Bs + (kt % STAGES) * BK * LDB_S;

        #pragma unroll
        for (int ks = 0; ks < 4; ks++) {
            const int kb = ks * 8;
            uint32_t af[4][4];
            uint32_t bf[4][2];
            #pragma unroll
            for (int tm = 0; tm < 4; tm++) {
                const float* ap = Asc + (wm + tm * 16) * LDA_S + kb;
                af[tm][0] = __float_as_uint(ap[g * LDA_S + t4]);
                af[tm][1] = __float_as_uint(ap[(g + 8) * LDA_S + t4]);
                af[tm][2] = __float_as_uint(ap[g * LDA_S + t4 + 4]);
                af[tm][3] = __float_as_uint(ap[(g + 8) * LDA_S + t4 + 4]);
            }
            #pragma unroll
            for (int tn = 0; tn < 4; tn++) {
                const float* bp = Bsc + kb * LDB_S + wn + tn * 8 + g;
                bf[tn][0] = __float_as_uint(bp[t4 * LDB_S]);
                bf[tn][1] = __float_as_uint(bp[(t4 + 4) * LDB_S]);
            }
            #pragma unroll
            for (int tm = 0; tm < 4; tm++) {
                #pragma unroll
                for (int tn = 0; tn < 4; tn++) {
                    asm volatile(
                        "mma.sync.aligned.m16n8k8.row.col.f32.tf32.tf32.f32 "
                        "{%0,%1,%2,%3}, {%4,%5,%6,%7}, {%8,%9}, {%0,%1,%2,%3};\n"
                        : "+f"(acc[tm][tn][0]), "+f"(acc[tm][tn][1]),
                          "+f"(acc[tm][tn][2]), "+f"(acc[tm][tn][3])
                        : "r"(af[tm][0]), "r"(af[tm][1]), "r"(af[tm][2]), "r"(af[tm][3]),
                          "r"(bf[tn][0]), "r"(bf[tn][1]));
                }
            }
        }
        __syncthreads();   // protect buf (kt%3) before it is refilled next iter
    }

    // ---- epilogue: C(n=m_row, c) -> out[b, n, e],  c = b*64 + e ----
    #pragma unroll
    for (int tm = 0; tm < 4; tm++) {
        #pragma unroll
        for (int tn = 0; tn < 4; tn++) {
            int m0 = bm * BM + wm + tm * 16 + g;
            int c0 = bn * BN + wn + tn * 8 + t4 * 2;
            int bb = c0 >> 6;
            int ee = c0 & 63;
            float2 v0 = make_float2(acc[tm][tn][0], acc[tm][tn][1]);
            float2 v1 = make_float2(acc[tm][tn][2], acc[tm][tn][3]);
            *reinterpret_cast<float2*>(out + ((size_t)(bb * 4096 + m0) * 64 + ee))       = v0;
            *reinterpret_cast<float2*>(out + ((size_t)(bb * 4096 + (m0 + 8)) * 64 + ee)) = v1;
        }
    }
}

// ---------------- launch ----------------
extern "C" void kernel_launch(void* const* d_in, const int* in_sizes, int n_in,
                              void* d_out, int out_size) {
    const float* Z = (const float*)d_in[0];   // [16, 4096, 64]
    const float* A = (const float*)d_in[1];   // [4096, 4096]
    const float* W = (const float*)d_in[2];   // [64, 64]
    float* out = (float*)d_out;               // [16, 4096, 64]
    (void)in_sizes; (void)n_in; (void)out_size;

    cudaFuncSetAttribute(gemm2_kernel,
                         cudaFuncAttributeMaxDynamicSharedMemorySize, SMEM_BYTES);

    convA_kernel<<<16384, 256>>>(reinterpret_cast<const float4*>(A));
    gemm1_kernel<<<2048, 256>>>(Z, W);
    gemm2_kernel<<<dim3(8, 32), 256, SMEM_BYTES>>>(out);
}

// round 7
// speedup vs baseline: 1.1937x; 1.1937x over previous
#include <cuda_runtime.h>
#include <cuda_bf16.h>
#include <cstdint>

// out[b,n,e] = sum_m A[n,m] * (sum_d Z[b,m,d] * W[d,e])
// B=16, N=4096, D_IN=64, D_OUT=64
//   gemm1: Xt[c][m] = sum_d Z[b,m,d]*W[d,e],  c = b*64+e   (Xt is [1024][4096], K-major)
//   gemm2: out(n,c)  = sum_m A[n,m] * Xt[c][m]   (M=4096,N=1024,K=4096, tf32 mma.sync + ldmatrix)

#define NROWS 4096
#define NCOLSX 1024
#define KDIM  4096

__device__ __align__(1024) float g_Atf[NROWS * KDIM];    // tf32-rounded A (64 MB)
__device__ __align__(1024) float g_Xt[NCOLSX * KDIM];    // tf32-rounded (Z@W)^T (16 MB)

// ---------------- helpers ----------------
__device__ __forceinline__ float tf32_round(float x) {
    uint32_t u;
    asm volatile("cvt.rna.tf32.f32 %0, %1;\n" : "=r"(u) : "f"(x));
    return __uint_as_float(u);
}
__device__ __forceinline__ uint32_t smem_u32(const void* p) {
    return (uint32_t)__cvta_generic_to_shared(p);
}
__device__ __forceinline__ void cp_async16_s(uint32_t dst_smem, const void* src) {
    asm volatile("cp.async.cg.shared.global [%0], [%1], 16;\n"
                 :: "r"(dst_smem), "l"(src) : "memory");
}
__device__ __forceinline__ void cp_commit() {
    asm volatile("cp.async.commit_group;\n" ::: "memory");
}
__device__ __forceinline__ void ldsm_x4(uint32_t& r0, uint32_t& r1, uint32_t& r2, uint32_t& r3,
                                        uint32_t addr) {
    asm volatile("ldmatrix.sync.aligned.m8n8.x4.shared.b16 {%0,%1,%2,%3}, [%4];\n"
                 : "=r"(r0), "=r"(r1), "=r"(r2), "=r"(r3) : "r"(addr) : "memory");
}

// ---------------- kernel 0: round A to tf32 ----------------
__global__ void __launch_bounds__(256) convA_kernel(const float4* __restrict__ A) {
    int i = blockIdx.x * 256 + threadIdx.x;   // 16384 * 256 = 4,194,304 float4
    float4 v = __ldg(A + i);
    float4 o;
    o.x = tf32_round(v.x); o.y = tf32_round(v.y);
    o.z = tf32_round(v.z); o.w = tf32_round(v.w);
    reinterpret_cast<float4*>(g_Atf)[i] = o;
}

// ---------------- kernel 1: Xt = (Z @ W)^T, tf32-rounded ----------------
// grid (64 m-tiles, 16 batches), 256 threads
__global__ void __launch_bounds__(256) gemm1_kernel(const float* __restrict__ Z,
                                                    const float* __restrict__ W) {
    __shared__ float Zs[64 * 65];
    __shared__ float Ws[64 * 64];
    const int tid = threadIdx.x;
    const int m0  = blockIdx.x * 64;
    const int b   = blockIdx.y;

    const float* Zg = Z + (size_t)((b << 12) + m0) * 64;
    #pragma unroll
    for (int r = 0; r < 4; r++) {
        int i = tid + r * 256;            // 1024 float4
        int row = i >> 4, c4 = (i & 15) * 4;
        float4 v = __ldg(reinterpret_cast<const float4*>(Zg + (size_t)row * 64 + c4));
        float* zp = Zs + row * 65 + c4;
        zp[0] = v.x; zp[1] = v.y; zp[2] = v.z; zp[3] = v.w;
    }
    #pragma unroll
    for (int r = 0; r < 4; r++) {
        int i = tid + r * 256;
        reinterpret_cast<float4*>(Ws)[i] = __ldg(reinterpret_cast<const float4*>(W) + i);
    }
    __syncthreads();

    const int ml = tid & 63;          // local m
    const int e0 = (tid >> 6) * 16;   // 16 e's per thread

    float acc[16];
    #pragma unroll
    for (int j = 0; j < 16; j++) acc[j] = 0.0f;

    #pragma unroll 4
    for (int d = 0; d < 64; d++) {
        float zv = Zs[ml * 65 + d];
        const float4* wp = reinterpret_cast<const float4*>(Ws + d * 64 + e0);
        #pragma unroll
        for (int q = 0; q < 4; q++) {
            float4 w = wp[q];
            acc[q * 4 + 0] = fmaf(zv, w.x, acc[q * 4 + 0]);
            acc[q * 4 + 1] = fmaf(zv, w.y, acc[q * 4 + 1]);
            acc[q * 4 + 2] = fmaf(zv, w.z, acc[q * 4 + 2]);
            acc[q * 4 + 3] = fmaf(zv, w.w, acc[q * 4 + 3]);
        }
    }

    // Xt[(b*64+e)][m0+ml], coalesced along ml
    #pragma unroll
    for (int j = 0; j < 16; j++) {
        g_Xt[(size_t)((b << 6) + e0 + j) * KDIM + m0 + ml] = tf32_round(acc[j]);
    }
}

// ---------------- kernel 2: out = A_tf @ Xt^T (tf32 mma + ldmatrix, 3-stage) ----------------
#define BM 128
#define BN 128
#define BK 32
#define STAGES 3
#define PITCH 36                     // floats per tile row (32 + 4 pad) -> conflict-free ldmatrix
#define TILE_F (128 * PITCH)         // 4608 floats per tile
#define KT (KDIM / BK)               // 128 k-tiles
#define SMEM_FLOATS (STAGES * TILE_F * 2)      // 27648
#define SMEM_BYTES  (SMEM_FLOATS * 4)          // 110592

__global__ void __launch_bounds__(256, 2) gemm2_kernel(float* __restrict__ out) {
    extern __shared__ float smem[];
    float* As = smem;                       // [STAGES][128][PITCH]
    float* Bs = smem + STAGES * TILE_F;     // [STAGES][128][PITCH] (n-major)

    const int tid  = threadIdx.x;
    const int wid  = tid >> 5;
    const int lane = tid & 31;
    const int g    = lane >> 2;    // 0..7
    const int t4   = lane & 3;     // 0..3
    const int wm   = (wid & 1) * 64;    // warp m-offset
    const int wn   = (wid >> 1) * 32;   // warp n-offset
    const int bm   = blockIdx.y;        // 0..31
    const int bn   = blockIdx.x;        // 0..7

    const float* Ag0 = g_Atf + (size_t)(bm * BM) * KDIM;
    const float* Bg0 = g_Xt  + (size_t)(bn * BN) * KDIM;

    const uint32_t As_u = smem_u32(As);
    const uint32_t Bs_u = smem_u32(Bs);

    // per-lane invariant ldmatrix offsets (in floats)
    //   A: lanes 0-15 -> rows (m), lanes/16 -> k-half; gives a0..a3 of m16n8k8
    //   B (n-major): lanes 0-7 rows n0-7 k0-3, 8-15 same rows k4-7, 16-31 rows n8-15
    const int a_off = (wm + (lane & 15)) * PITCH + (lane >> 4) * 4;
    const int b_off = (wn + ((lane >> 4) << 3) + (lane & 7)) * PITCH + ((lane >> 3) & 1) * 4;

    // ---- async tile loader (A and B identical: 128 rows x 32 k, K-major) ----
    auto load_tile = [&](int kt, int s) {
        const float* Ag = Ag0 + kt * BK;
        uint32_t Asd = As_u + (s * TILE_F) * 4;
        #pragma unroll
        for (int r = 0; r < 4; r++) {
            int i   = tid + r * 256;      // 1024 float4
            int row = i >> 3;
            int cv  = (i & 7) * 4;
            cp_async16_s(Asd + (row * PITCH + cv) * 4, Ag + (size_t)row * KDIM + cv);
        }
        const float* Bg = Bg0 + kt * BK;
        uint32_t Bsd = Bs_u + (s * TILE_F) * 4;
        #pragma unroll
        for (int r = 0; r < 4; r++) {
            int i   = tid + r * 256;
            int row = i >> 3;
            int cv  = (i & 7) * 4;
            cp_async16_s(Bsd + (row * PITCH + cv) * 4, Bg + (size_t)row * KDIM + cv);
        }
    };

    float acc[4][4][4];
    #pragma unroll
    for (int a = 0; a < 4; a++)
        #pragma unroll
        for (int b = 0; b < 4; b++)
            #pragma unroll
            for (int c = 0; c < 4; c++) acc[a][b][c] = 0.0f;

    load_tile(0, 0); cp_commit();
    load_tile(1, 1); cp_commit();

    for (int kt = 0; kt < KT; kt++) {
        int lt = kt + 2;
        if (lt < KT) load_tile(lt, lt % STAGES);
        cp_commit();
        asm volatile("cp.async.wait_group 1;\n" ::: "memory");
        __syncthreads();

        const uint32_t Asc = As_u + ((kt % STAGES) * TILE_F) * 4;
        const uint32_t Bsc = Bs_u + ((kt % STAGES) * TILE_F) * 4;

        #pragma unroll
        for (int ks = 0; ks < 4; ks++) {
            const int kb = ks * 8;
            uint32_t af[4][4];
            uint32_t bf[4][2];
            #pragma unroll
            for (int tm = 0; tm < 4; tm++) {
                ldsm_x4(af[tm][0], af[tm][1], af[tm][2], af[tm][3],
                        Asc + (a_off + tm * 16 * PITCH + kb) * 4);
            }
            #pragma unroll
            for (int p = 0; p < 2; p++) {
                ldsm_x4(bf[2 * p][0], bf[2 * p][1], bf[2 * p + 1][0], bf[2 * p + 1][1],
                        Bsc + (b_off + p * 16 * PITCH + kb) * 4);
            }
            #pragma unroll
            for (int tm = 0; tm < 4; tm++) {
                #pragma unroll
                for (int tn = 0; tn < 4; tn++) {
                    asm volatile(
                        "mma.sync.aligned.m16n8k8.row.col.f32.tf32.tf32.f32 "
                        "{%0,%1,%2,%3}, {%4,%5,%6,%7}, {%8,%9}, {%0,%1,%2,%3};\n"
                        : "+f"(acc[tm][tn][0]), "+f"(acc[tm][tn][1]),
                          "+f"(acc[tm][tn][2]), "+f"(acc[tm][tn][3])
                        : "r"(af[tm][0]), "r"(af[tm][1]), "r"(af[tm][2]), "r"(af[tm][3]),
                          "r"(bf[tn][0]), "r"(bf[tn][1]));
                }
            }
        }
        __syncthreads();
    }

    // ---- epilogue: C(n=m_row, c) -> out[b, n, e],  c = b*64 + e ----
    #pragma unroll
    for (int tm = 0; tm < 4; tm++) {
        #pragma unroll
        for (int tn = 0; tn < 4; tn++) {
            int m0 = bm * BM + wm + tm * 16 + g;
            int c0 = bn * BN + wn + tn * 8 + t4 * 2;
            int bb = c0 >> 6;
            int ee = c0 & 63;
            float2 v0 = make_float2(acc[tm][tn][0], acc[tm][tn][1]);
            float2 v1 = make_float2(acc[tm][tn][2], acc[tm][tn][3]);
            *reinterpret_cast<float2*>(out + ((size_t)(bb * 4096 + m0) * 64 + ee))       = v0;
            *reinterpret_cast<float2*>(out + ((size_t)(bb * 4096 + (m0 + 8)) * 64 + ee)) = v1;
        }
    }
}

// ---------------- launch ----------------
extern "C" void kernel_launch(void* const* d_in, const int* in_sizes, int n_in,
                              void* d_out, int out_size) {
    const float* Z = (const float*)d_in[0];   // [16, 4096, 64]
    const float* A = (const float*)d_in[1];   // [4096, 4096]
    const float* W = (const float*)d_in[2];   // [64, 64]
    float* out = (float*)d_out;               // [16, 4096, 64]
    (void)in_sizes; (void)n_in; (void)out_size;

    cudaFuncSetAttribute(gemm2_kernel,
                         cudaFuncAttributeMaxDynamicSharedMemorySize, SMEM_BYTES);

    convA_kernel<<<16384, 256>>>(reinterpret_cast<const float4*>(A));
    gemm1_kernel<<<dim3(64, 16), 256>>>(Z, W);
    gemm2_kernel<<<dim3(8, 32), 256, SMEM_BYTES>>>(out);
}

// round 8
// speedup vs baseline: 1.2616x; 1.0569x over previous
#include <cuda_runtime.h>
#include <cuda_bf16.h>
#include <cstdint>

// out[b,n,e] = sum_m A[n,m] * (sum_d Z[b,m,d] * W[d,e])
// B=16, N=4096, D_IN=64, D_OUT=64
//   gemm1: Xt[c][m] = sum_d Z[b,m,d]*W[d,e],  c = b*64+e   (Xt [1024][4096], K-major, tf32-rna)
//   gemm2: out(n,c)  = sum_m A[n,m] * Xt[c][m]   (M=4096,N=1024,K=4096)
//          A is fed raw (implicit RZ tf32 truncation by HMMA); X is rna-rounded.

#define NCOLSX 1024
#define KDIM  4096

__device__ __align__(1024) float g_Xt[NCOLSX * KDIM];    // tf32-rounded (Z@W)^T (16 MB)

// ---------------- helpers ----------------
__device__ __forceinline__ float tf32_round(float x) {
    uint32_t u;
    asm volatile("cvt.rna.tf32.f32 %0, %1;\n" : "=r"(u) : "f"(x));
    return __uint_as_float(u);
}
__device__ __forceinline__ uint32_t smem_u32(const void* p) {
    return (uint32_t)__cvta_generic_to_shared(p);
}
__device__ __forceinline__ void cp_async16_s(uint32_t dst_smem, const void* src) {
    asm volatile("cp.async.cg.shared.global [%0], [%1], 16;\n"
                 :: "r"(dst_smem), "l"(src) : "memory");
}
__device__ __forceinline__ void cp_commit() {
    asm volatile("cp.async.commit_group;\n" ::: "memory");
}
__device__ __forceinline__ void ldsm_x4(uint32_t& r0, uint32_t& r1, uint32_t& r2, uint32_t& r3,
                                        uint32_t addr) {
    asm volatile("ldmatrix.sync.aligned.m8n8.x4.shared.b16 {%0,%1,%2,%3}, [%4];\n"
                 : "=r"(r0), "=r"(r1), "=r"(r2), "=r"(r3) : "r"(addr) : "memory");
}

// ---------------- kernel 1: Xt = (Z @ W)^T, tf32-rounded ----------------
__global__ void __launch_bounds__(256) gemm1_kernel(const float* __restrict__ Z,
                                                    const float* __restrict__ W) {
    __shared__ float Zs[64 * 65];
    __shared__ float Ws[64 * 64];
    const int tid = threadIdx.x;
    const int m0  = blockIdx.x * 64;
    const int b   = blockIdx.y;

    const float* Zg = Z + (size_t)((b << 12) + m0) * 64;
    #pragma unroll
    for (int r = 0; r < 4; r++) {
        int i = tid + r * 256;            // 1024 float4
        int row = i >> 4, c4 = (i & 15) * 4;
        float4 v = __ldg(reinterpret_cast<const float4*>(Zg + (size_t)row * 64 + c4));
        float* zp = Zs + row * 65 + c4;
        zp[0] = v.x; zp[1] = v.y; zp[2] = v.z; zp[3] = v.w;
    }
    #pragma unroll
    for (int r = 0; r < 4; r++) {
        int i = tid + r * 256;
        reinterpret_cast<float4*>(Ws)[i] = __ldg(reinterpret_cast<const float4*>(W) + i);
    }
    __syncthreads();

    const int ml = tid & 63;
    const int e0 = (tid >> 6) * 16;

    float acc[16];
    #pragma unroll
    for (int j = 0; j < 16; j++) acc[j] = 0.0f;

    #pragma unroll 4
    for (int d = 0; d < 64; d++) {
        float zv = Zs[ml * 65 + d];
        const float4* wp = reinterpret_cast<const float4*>(Ws + d * 64 + e0);
        #pragma unroll
        for (int q = 0; q < 4; q++) {
            float4 w = wp[q];
            acc[q * 4 + 0] = fmaf(zv, w.x, acc[q * 4 + 0]);
            acc[q * 4 + 1] = fmaf(zv, w.y, acc[q * 4 + 1]);
            acc[q * 4 + 2] = fmaf(zv, w.z, acc[q * 4 + 2]);
            acc[q * 4 + 3] = fmaf(zv, w.w, acc[q * 4 + 3]);
        }
    }

    #pragma unroll
    for (int j = 0; j < 16; j++) {
        g_Xt[(size_t)((b << 6) + e0 + j) * KDIM + m0 + ml] = tf32_round(acc[j]);
    }
}

// ---------------- kernel 2: out = A @ Xt^T (tf32 mma + ldmatrix, 3-stage) ----------------
// 128 threads, 4 warps, warp tile 64x64, CTA tile 128x128
#define BM 128
#define BN 128
#define BK 32
#define STAGES 3
#define PITCH 36                     // 32 + 4 pad floats -> conflict-free ldmatrix
#define TILE_F (128 * PITCH)         // 4608 floats per tile
#define KT (KDIM / BK)               // 128 k-tiles
#define SMEM_FLOATS (STAGES * TILE_F * 2)      // 27648
#define SMEM_BYTES  (SMEM_FLOATS * 4)          // 110592

__global__ void __launch_bounds__(128, 2) gemm2_kernel(const float* __restrict__ Ain,
                                                       float* __restrict__ out) {
    extern __shared__ float smem[];
    float* As = smem;                       // [STAGES][128][PITCH]  (m-rows, K-major)
    float* Bs = smem + STAGES * TILE_F;     // [STAGES][128][PITCH]  (n-rows, K-major)

    const int tid  = threadIdx.x;
    const int wid  = tid >> 5;
    const int lane = tid & 31;
    const int g    = lane >> 2;    // 0..7
    const int t4   = lane & 3;     // 0..3
    const int wm   = (wid & 1) * 64;    // warp m-offset (2 warps along M)
    const int wn   = (wid >> 1) * 64;   // warp n-offset (2 warps along N)
    const int bm   = blockIdx.y;        // 0..31
    const int bn   = blockIdx.x;        // 0..7

    const float* Ag0 = Ain  + (size_t)(bm * BM) * KDIM;
    const float* Bg0 = g_Xt + (size_t)(bn * BN) * KDIM;

    const uint32_t As_u = smem_u32(As);
    const uint32_t Bs_u = smem_u32(Bs);

    // ldmatrix per-lane offsets (floats):
    //   A x4 covers 16 m-rows x 8 k (two 4-k halves) -> a0..a3 of m16n8k8
    //   B x4 covers 16 n-rows x 8 k -> b0/b1 for two n8 tiles
    const int a_off = (wm + (lane & 15)) * PITCH + (lane >> 4) * 4;
    const int b_off = (wn + ((lane >> 4) << 3) + (lane & 7)) * PITCH + ((lane >> 3) & 1) * 4;

    // ---- async tile loader: A and B each 128 rows x 32 k ----
    auto load_tile = [&](int kt, int s) {
        const float* Ag = Ag0 + kt * BK;
        uint32_t Asd = As_u + (s * TILE_F) * 4;
        #pragma unroll
        for (int r = 0; r < 8; r++) {
            int i   = tid + r * 128;      // 1024 float4
            int row = i >> 3;
            int cv  = (i & 7) * 4;
            cp_async16_s(Asd + (row * PITCH + cv) * 4, Ag + (size_t)row * KDIM + cv);
        }
        const float* Bg = Bg0 + kt * BK;
        uint32_t Bsd = Bs_u + (s * TILE_F) * 4;
        #pragma unroll
        for (int r = 0; r < 8; r++) {
            int i   = tid + r * 128;
            int row = i >> 3;
            int cv  = (i & 7) * 4;
            cp_async16_s(Bsd + (row * PITCH + cv) * 4, Bg + (size_t)row * KDIM + cv);
        }
    };

    float acc[4][8][4];
    #pragma unroll
    for (int a = 0; a < 4; a++)
        #pragma unroll
        for (int b = 0; b < 8; b++)
            #pragma unroll
            for (int c = 0; c < 4; c++) acc[a][b][c] = 0.0f;

    load_tile(0, 0); cp_commit();
    load_tile(1, 1); cp_commit();

    for (int kt = 0; kt < KT; kt++) {
        int lt = kt + 2;
        if (lt < KT) load_tile(lt, lt % STAGES);
        cp_commit();
        // allow the 2 most recent groups (kt+1, kt+2) to remain in flight;
        // only require tile kt complete -> true prefetch distance 2
        asm volatile("cp.async.wait_group 2;\n" ::: "memory");
        __syncthreads();

        const uint32_t Asc = As_u + ((kt % STAGES) * TILE_F) * 4;
        const uint32_t Bsc = Bs_u + ((kt % STAGES) * TILE_F) * 4;

        #pragma unroll
        for (int ks = 0; ks < 4; ks++) {
            const int kb = ks * 8;
            uint32_t af[4][4];
            uint32_t bf[8][2];
            #pragma unroll
            for (int tm = 0; tm < 4; tm++) {
                ldsm_x4(af[tm][0], af[tm][1], af[tm][2], af[tm][3],
                        Asc + (a_off + tm * 16 * PITCH + kb) * 4);
            }
            #pragma unroll
            for (int q = 0; q < 4; q++) {
                ldsm_x4(bf[2 * q][0], bf[2 * q][1], bf[2 * q + 1][0], bf[2 * q + 1][1],
                        Bsc + (b_off + q * 16 * PITCH + kb) * 4);
            }
            #pragma unroll
            for (int tm = 0; tm < 4; tm++) {
                #pragma unroll
                for (int tn = 0; tn < 8; tn++) {
                    asm volatile(
                        "mma.sync.aligned.m16n8k8.row.col.f32.tf32.tf32.f32 "
                        "{%0,%1,%2,%3}, {%4,%5,%6,%7}, {%8,%9}, {%0,%1,%2,%3};\n"
                        : "+f"(acc[tm][tn][0]), "+f"(acc[tm][tn][1]),
                          "+f"(acc[tm][tn][2]), "+f"(acc[tm][tn][3])
                        : "r"(af[tm][0]), "r"(af[tm][1]), "r"(af[tm][2]), "r"(af[tm][3]),
                          "r"(bf[tn][0]), "r"(bf[tn][1]));
                }
            }
        }
        __syncthreads();   // protect stage (kt%3) before next-iteration refill
    }

    // ---- epilogue: C(n=m_row, c) -> out[b, n, e],  c = b*64 + e ----
    #pragma unroll
    for (int tm = 0; tm < 4; tm++) {
        #pragma unroll
        for (int tn = 0; tn < 8; tn++) {
            int m0 = bm * BM + wm + tm * 16 + g;
            int c0 = bn * BN + wn + tn * 8 + t4 * 2;
            int bb = c0 >> 6;
            int ee = c0 & 63;
            float2 v0 = make_float2(acc[tm][tn][0], acc[tm][tn][1]);
            float2 v1 = make_float2(acc[tm][tn][2], acc[tm][tn][3]);
            *reinterpret_cast<float2*>(out + ((size_t)(bb * 4096 + m0) * 64 + ee))       = v0;
            *reinterpret_cast<float2*>(out + ((size_t)(bb * 4096 + (m0 + 8)) * 64 + ee)) = v1;
        }
    }
}

// ---------------- launch ----------------
extern "C" void kernel_launch(void* const* d_in, const int* in_sizes, int n_in,
                              void* d_out, int out_size) {
    const float* Z = (const float*)d_in[0];   // [16, 4096, 64]
    const float* A = (const float*)d_in[1];   // [4096, 4096]
    const float* W = (const float*)d_in[2];   // [64, 64]
    float* out = (float*)d_out;               // [16, 4096, 64]
    (void)in_sizes; (void)n_in; (void)out_size;

    cudaFuncSetAttribute(gemm2_kernel,
                         cudaFuncAttributeMaxDynamicSharedMemorySize, SMEM_BYTES);

    gemm1_kernel<<<dim3(64, 16), 256>>>(Z, W);
    gemm2_kernel<<<dim3(8, 32), 128, SMEM_BYTES>>>(A, out);
}

// round 9
// speedup vs baseline: 1.3045x; 1.0340x over previous
#include <cuda_runtime.h>
#include <cuda_bf16.h>
#include <cstdint>

// out[b,n,e] = sum_m A[n,m] * (sum_d Z[b,m,d] * W[d,e])
// B=16, N=4096, D_IN=64, D_OUT=64
//   gemm1: Xt[c][m] = sum_d Z[b,m,d]*W[d,e],  c = b*64+e   (Xt [1024][4096], K-major, tf32-rna)
//   gemm2: out(n,c)  = sum_m A[n,m] * Xt[c][m]   (M=4096,N=1024,K=4096)
//          A fed raw (implicit RZ tf32 truncation in HMMA); X rna-rounded.

#define NCOLSX 1024
#define KDIM  4096

__device__ __align__(1024) float g_Xt[NCOLSX * KDIM];    // tf32-rounded (Z@W)^T (16 MB)

// ---------------- helpers ----------------
__device__ __forceinline__ float tf32_round(float x) {
    uint32_t u;
    asm volatile("cvt.rna.tf32.f32 %0, %1;\n" : "=r"(u) : "f"(x));
    return __uint_as_float(u);
}
__device__ __forceinline__ uint32_t smem_u32(const void* p) {
    return (uint32_t)__cvta_generic_to_shared(p);
}
__device__ __forceinline__ void cp_async16_s(uint32_t dst_smem, const void* src) {
    asm volatile("cp.async.cg.shared.global [%0], [%1], 16;\n"
                 :: "r"(dst_smem), "l"(src) : "memory");
}
__device__ __forceinline__ void cp_commit() {
    asm volatile("cp.async.commit_group;\n" ::: "memory");
}
__device__ __forceinline__ void ldsm_x4(uint32_t& r0, uint32_t& r1, uint32_t& r2, uint32_t& r3,
                                        uint32_t addr) {
    asm volatile("ldmatrix.sync.aligned.m8n8.x4.shared.b16 {%0,%1,%2,%3}, [%4];\n"
                 : "=r"(r0), "=r"(r1), "=r"(r2), "=r"(r3) : "r"(addr) : "memory");
}

// ---------------- kernel 1: Xt = (Z @ W)^T, tf32-rounded ----------------
__global__ void __launch_bounds__(256) gemm1_kernel(const float* __restrict__ Z,
                                                    const float* __restrict__ W) {
    __shared__ float Zs[64 * 65];
    __shared__ float Ws[64 * 64];
    const int tid = threadIdx.x;
    const int m0  = blockIdx.x * 64;
    const int b   = blockIdx.y;

    const float* Zg = Z + (size_t)((b << 12) + m0) * 64;
    #pragma unroll
    for (int r = 0; r < 4; r++) {
        int i = tid + r * 256;            // 1024 float4
        int row = i >> 4, c4 = (i & 15) * 4;
        float4 v = __ldg(reinterpret_cast<const float4*>(Zg + (size_t)row * 64 + c4));
        float* zp = Zs + row * 65 + c4;
        zp[0] = v.x; zp[1] = v.y; zp[2] = v.z; zp[3] = v.w;
    }
    #pragma unroll
    for (int r = 0; r < 4; r++) {
        int i = tid + r * 256;
        reinterpret_cast<float4*>(Ws)[i] = __ldg(reinterpret_cast<const float4*>(W) + i);
    }
    __syncthreads();

    const int ml = tid & 63;
    const int e0 = (tid >> 6) * 16;

    float acc[16];
    #pragma unroll
    for (int j = 0; j < 16; j++) acc[j] = 0.0f;

    #pragma unroll 4
    for (int d = 0; d < 64; d++) {
        float zv = Zs[ml * 65 + d];
        const float4* wp = reinterpret_cast<const float4*>(Ws + d * 64 + e0);
        #pragma unroll
        for (int q = 0; q < 4; q++) {
            float4 w = wp[q];
            acc[q * 4 + 0] = fmaf(zv, w.x, acc[q * 4 + 0]);
            acc[q * 4 + 1] = fmaf(zv, w.y, acc[q * 4 + 1]);
            acc[q * 4 + 2] = fmaf(zv, w.z, acc[q * 4 + 2]);
            acc[q * 4 + 3] = fmaf(zv, w.w, acc[q * 4 + 3]);
        }
    }

    #pragma unroll
    for (int j = 0; j < 16; j++) {
        g_Xt[(size_t)((b << 6) + e0 + j) * KDIM + m0 + ml] = tf32_round(acc[j]);
    }
}

// ---------------- kernel 2: out = A @ Xt^T (tf32 mma + ldmatrix) ----------------
// CTA tile 128(M) x 256(N), 256 threads / 8 warps (2 along M x 4 along N),
// warp tile 64x64, BK=32, 4 stages, single __syncthreads per k-tile.
#define BM 128
#define BN 256
#define BK 32
#define STAGES 4
#define PITCH 36                       // 32 + 4 pad floats -> conflict-free ldmatrix
#define A_TILE_F (BM * PITCH)          // 4608 floats
#define B_TILE_F (BN * PITCH)          // 9216 floats
#define STAGE_F  (A_TILE_F + B_TILE_F) // 13824 floats
#define KT (KDIM / BK)                 // 128 k-tiles
#define SMEM_BYTES (STAGES * STAGE_F * 4)   // 221184

__global__ void __launch_bounds__(256, 1) gemm2_kernel(const float* __restrict__ Ain,
                                                       float* __restrict__ out) {
    extern __shared__ float smem[];

    const int tid  = threadIdx.x;
    const int wid  = tid >> 5;
    const int lane = tid & 31;
    const int g    = lane >> 2;    // 0..7
    const int t4   = lane & 3;     // 0..3
    const int wm   = (wid & 1) * 64;    // 2 warps along M
    const int wn   = (wid >> 1) * 64;   // 4 warps along N
    const int bm   = blockIdx.y;        // 0..31
    const int bn   = blockIdx.x;        // 0..3

    const float* Ag0 = Ain  + (size_t)(bm * BM) * KDIM;
    const float* Bg0 = g_Xt + (size_t)(bn * BN) * KDIM;

    const uint32_t S_u = smem_u32(smem);

    // ldmatrix per-lane offsets (floats), relative to a stage's A / B base:
    //   A x4: 16 m-rows x 8 k -> a0..a3 of m16n8k8
    //   B x4 (n-major): 16 n-rows x 8 k -> b0/b1 for two n8 tiles
    const int a_off = (wm + (lane & 15)) * PITCH + (lane >> 4) * 4;
    const int b_off = (wn + ((lane >> 4) << 3) + (lane & 7)) * PITCH + ((lane >> 3) & 1) * 4;

    // ---- async tile loader: A 128 rows x 32k, B 256 rows x 32k (both K-major) ----
    auto load_tile = [&](int kt, int s) {
        const uint32_t Sb = S_u + (s * STAGE_F) * 4;
        const float* Ag = Ag0 + kt * BK;
        #pragma unroll
        for (int r = 0; r < 4; r++) {
            int i   = tid + r * 256;      // 1024 float4 (A)
            int row = i >> 3;
            int cv  = (i & 7) * 4;
            cp_async16_s(Sb + (row * PITCH + cv) * 4, Ag + (size_t)row * KDIM + cv);
        }
        const float* Bg = Bg0 + kt * BK;
        const uint32_t Bb = Sb + A_TILE_F * 4;
        #pragma unroll
        for (int r = 0; r < 8; r++) {
            int i   = tid + r * 256;      // 2048 float4 (B)
            int row = i >> 3;
            int cv  = (i & 7) * 4;
            cp_async16_s(Bb + (row * PITCH + cv) * 4, Bg + (size_t)row * KDIM + cv);
        }
    };

    float acc[4][8][4];
    #pragma unroll
    for (int a = 0; a < 4; a++)
        #pragma unroll
        for (int b = 0; b < 8; b++)
            #pragma unroll
            for (int c = 0; c < 4; c++) acc[a][b][c] = 0.0f;

    load_tile(0, 0); cp_commit();
    load_tile(1, 1); cp_commit();
    load_tile(2, 2); cp_commit();

    for (int kt = 0; kt < KT; kt++) {
        // tile kt complete (groups kt+1, kt+2 may stay in flight)
        asm volatile("cp.async.wait_group 2;\n" ::: "memory");
        __syncthreads();   // all warps done reading stage (kt+3)%4 (read at iter kt-1)

        int lt = kt + 3;
        if (lt < KT) load_tile(lt, lt & 3);
        cp_commit();

        const uint32_t Asc = S_u + ((kt & 3) * STAGE_F) * 4;
        const uint32_t Bsc = Asc + A_TILE_F * 4;

        #pragma unroll
        for (int ks = 0; ks < 4; ks++) {
            const int kb = ks * 8;
            uint32_t af[4][4];
            uint32_t bf[8][2];
            #pragma unroll
            for (int tm = 0; tm < 4; tm++) {
                ldsm_x4(af[tm][0], af[tm][1], af[tm][2], af[tm][3],
                        Asc + (a_off + tm * 16 * PITCH + kb) * 4);
            }
            #pragma unroll
            for (int q = 0; q < 4; q++) {
                ldsm_x4(bf[2 * q][0], bf[2 * q][1], bf[2 * q + 1][0], bf[2 * q + 1][1],
                        Bsc + (b_off + q * 16 * PITCH + kb) * 4);
            }
            #pragma unroll
            for (int tm = 0; tm < 4; tm++) {
                #pragma unroll
                for (int tn = 0; tn < 8; tn++) {
                    asm volatile(
                        "mma.sync.aligned.m16n8k8.row.col.f32.tf32.tf32.f32 "
                        "{%0,%1,%2,%3}, {%4,%5,%6,%7}, {%8,%9}, {%0,%1,%2,%3};\n"
                        : "+f"(acc[tm][tn][0]), "+f"(acc[tm][tn][1]),
                          "+f"(acc[tm][tn][2]), "+f"(acc[tm][tn][3])
                        : "r"(af[tm][0]), "r"(af[tm][1]), "r"(af[tm][2]), "r"(af[tm][3]),
                          "r"(bf[tn][0]), "r"(bf[tn][1]));
                }
            }
        }
    }

    // ---- epilogue: C(n=m_row, c) -> out[b, n, e],  c = b*64 + e ----
    #pragma unroll
    for (int tm = 0; tm < 4; tm++) {
        #pragma unroll
        for (int tn = 0; tn < 8; tn++) {
            int m0 = bm * BM + wm + tm * 16 + g;
            int c0 = bn * BN + wn + tn * 8 + t4 * 2;
            int bb = c0 >> 6;
            int ee = c0 & 63;
            float2 v0 = make_float2(acc[tm][tn][0], acc[tm][tn][1]);
            float2 v1 = make_float2(acc[tm][tn][2], acc[tm][tn][3]);
            *reinterpret_cast<float2*>(out + ((size_t)(bb * 4096 + m0) * 64 + ee))       = v0;
            *reinterpret_cast<float2*>(out + ((size_t)(bb * 4096 + (m0 + 8)) * 64 + ee)) = v1;
        }
    }
}

// ---------------- launch ----------------
extern "C" void kernel_launch(void* const* d_in, const int* in_sizes, int n_in,
                              void* d_out, int out_size) {
    const float* Z = (const float*)d_in[0];   // [16, 4096, 64]
    const float* A = (const float*)d_in[1];   // [4096, 4096]
    const float* W = (const float*)d_in[2];   // [64, 64]
    float* out = (float*)d_out;               // [16, 4096, 64]
    (void)in_sizes; (void)n_in; (void)out_size;

    cudaFuncSetAttribute(gemm2_kernel,
                         cudaFuncAttributeMaxDynamicSharedMemorySize, SMEM_BYTES);

    gemm1_kernel<<<dim3(64, 16), 256>>>(Z, W);
    gemm2_kernel<<<dim3(4, 32), 256, SMEM_BYTES>>>(A, out);
}

// round 10
// speedup vs baseline: 2.0381x; 1.5624x over previous
#include <cuda_runtime.h>
#include <cuda_fp16.h>
#include <cstdint>

// out[b,n,e] = sum_m A[n,m] * (sum_d Z[b,m,d] * W[d,e])
// B=16, N=4096, D_IN=64, D_OUT=64
//   convA: A_h = fp16(A)                          [4096][4096] half, K-major
//   gemm1: Xt[c][m] = fp16(sum_d Z[b,m,d]*W[d,e]) [1024][4096] half, K-major (c=b*64+e)
//   gemm2: out(n,c) = sum_m A_h[n][m]*Xt[c][m]    fp16 mma m16n8k16, fp32 accum

#define NCOLSX 1024
#define KDIM  4096

__device__ __align__(1024) __half g_Ah[4096 * KDIM];     // fp16 A (32 MB)
__device__ __align__(1024) __half g_Xt[NCOLSX * KDIM];   // fp16 (Z@W)^T (8 MB)

// ---------------- helpers ----------------
__device__ __forceinline__ uint32_t smem_u32(const void* p) {
    return (uint32_t)__cvta_generic_to_shared(p);
}
__device__ __forceinline__ void cp_async16_s(uint32_t dst_smem, const void* src) {
    asm volatile("cp.async.cg.shared.global [%0], [%1], 16;\n"
                 :: "r"(dst_smem), "l"(src) : "memory");
}
__device__ __forceinline__ void cp_commit() {
    asm volatile("cp.async.commit_group;\n" ::: "memory");
}
__device__ __forceinline__ void ldsm_x4(uint32_t& r0, uint32_t& r1, uint32_t& r2, uint32_t& r3,
                                        uint32_t addr) {
    asm volatile("ldmatrix.sync.aligned.m8n8.x4.shared.b16 {%0,%1,%2,%3}, [%4];\n"
                 : "=r"(r0), "=r"(r1), "=r"(r2), "=r"(r3) : "r"(addr) : "memory");
}

// ---------------- kernel 0: A -> fp16 ----------------
__global__ void __launch_bounds__(256) convA_kernel(const float4* __restrict__ A) {
    int i = blockIdx.x * 256 + threadIdx.x;   // 16384 * 256 = 4,194,304 float4
    float4 v = __ldg(A + i);
    __half2 h0 = __floats2half2_rn(v.x, v.y);
    __half2 h1 = __floats2half2_rn(v.z, v.w);
    uint2 o;
    o.x = *reinterpret_cast<uint32_t*>(&h0);
    o.y = *reinterpret_cast<uint32_t*>(&h1);
    reinterpret_cast<uint2*>(g_Ah)[i] = o;
}

// ---------------- kernel 1: Xt = fp16((Z @ W)^T) ----------------
__global__ void __launch_bounds__(256) gemm1_kernel(const float* __restrict__ Z,
                                                    const float* __restrict__ W) {
    __shared__ float Zs[64 * 65];
    __shared__ float Ws[64 * 64];
    const int tid = threadIdx.x;
    const int m0  = blockIdx.x * 64;
    const int b   = blockIdx.y;

    const float* Zg = Z + (size_t)((b << 12) + m0) * 64;
    #pragma unroll
    for (int r = 0; r < 4; r++) {
        int i = tid + r * 256;            // 1024 float4
        int row = i >> 4, c4 = (i & 15) * 4;
        float4 v = __ldg(reinterpret_cast<const float4*>(Zg + (size_t)row * 64 + c4));
        float* zp = Zs + row * 65 + c4;
        zp[0] = v.x; zp[1] = v.y; zp[2] = v.z; zp[3] = v.w;
    }
    #pragma unroll
    for (int r = 0; r < 4; r++) {
        int i = tid + r * 256;
        reinterpret_cast<float4*>(Ws)[i] = __ldg(reinterpret_cast<const float4*>(W) + i);
    }
    __syncthreads();

    const int ml = tid & 63;
    const int e0 = (tid >> 6) * 16;

    float acc[16];
    #pragma unroll
    for (int j = 0; j < 16; j++) acc[j] = 0.0f;

    #pragma unroll 4
    for (int d = 0; d < 64; d++) {
        float zv = Zs[ml * 65 + d];
        const float4* wp = reinterpret_cast<const float4*>(Ws + d * 64 + e0);
        #pragma unroll
        for (int q = 0; q < 4; q++) {
            float4 w = wp[q];
            acc[q * 4 + 0] = fmaf(zv, w.x, acc[q * 4 + 0]);
            acc[q * 4 + 1] = fmaf(zv, w.y, acc[q * 4 + 1]);
            acc[q * 4 + 2] = fmaf(zv, w.z, acc[q * 4 + 2]);
            acc[q * 4 + 3] = fmaf(zv, w.w, acc[q * 4 + 3]);
        }
    }

    #pragma unroll
    for (int j = 0; j < 16; j++) {
        g_Xt[(size_t)((b << 6) + e0 + j) * KDIM + m0 + ml] = __float2half_rn(acc[j]);
    }
}

// ---------------- kernel 2: out = A_h @ Xt^T (fp16 mma m16n8k16) ----------------
// CTA tile 128(M) x 256(N), 256 threads / 8 warps (2 along M x 4 along N),
// warp tile 64x64, BK=64 halves (128B rows), 4 stages, single sync per k-tile.
#define BM 128
#define BN 256
#define BK 64                          // halves per k-tile row
#define STAGES 4
#define PITCH 72                       // 64 + 8 pad halves (144 B) -> conflict-free ldmatrix
#define A_TILE_H (BM * PITCH)          // 9216 halves (18432 B)
#define B_TILE_H (BN * PITCH)          // 18432 halves (36864 B)
#define STAGE_H  (A_TILE_H + B_TILE_H) // 27648 halves (55296 B)
#define KT (KDIM / BK)                 // 64 k-tiles
#define SMEM_BYTES (STAGES * STAGE_H * 2)   // 221184

__global__ void __launch_bounds__(256, 1) gemm2_kernel(float* __restrict__ out) {
    extern __shared__ __half smem[];

    const int tid  = threadIdx.x;
    const int wid  = tid >> 5;
    const int lane = tid & 31;
    const int g    = lane >> 2;    // 0..7
    const int t4   = lane & 3;     // 0..3
    const int wm   = (wid & 1) * 64;    // 2 warps along M
    const int wn   = (wid >> 1) * 64;   // 4 warps along N
    const int bm   = blockIdx.y;        // 0..31
    const int bn   = blockIdx.x;        // 0..3

    const __half* Ag0 = g_Ah + (size_t)(bm * BM) * KDIM;
    const __half* Bg0 = g_Xt + (size_t)(bn * BN) * KDIM;

    const uint32_t S_u = smem_u32(smem);

    // ldmatrix per-lane offsets (halves), relative to stage A / B bases:
    //   A x4 (m16 x k16): lanes 0-7 rows m0-7 @k0, 8-15 m8-15 @k0,
    //                     16-23 m0-7 @k8, 24-31 m8-15 @k8 -> a0..a3 of m16n8k16
    //   B x4 (n-major, two n8 tiles x k16): lanes 0-7 n0-7 @k0, 8-15 n0-7 @k8,
    //                     16-23 n8-15 @k0, 24-31 n8-15 @k8 -> (b0,b1) x 2 tiles
    const int a_off = (wm + (lane & 15)) * PITCH + (lane >> 4) * 8;
    const int b_off = (wn + ((lane >> 4) << 3) + (lane & 7)) * PITCH + ((lane >> 3) & 1) * 8;

    // ---- async tile loader: A 128 rows x 64 halves, B 256 rows x 64 halves ----
    auto load_tile = [&](int kt, int s) {
        const uint32_t Sb = S_u + (s * STAGE_H) * 2;
        const __half* Ag = Ag0 + kt * BK;
        #pragma unroll
        for (int r = 0; r < 4; r++) {
            int i   = tid + r * 256;      // 1024 chunks of 16 B (8 halves)
            int row = i >> 3;
            int cv  = (i & 7) * 8;
            cp_async16_s(Sb + (row * PITCH + cv) * 2, Ag + (size_t)row * KDIM + cv);
        }
        const __half* Bg = Bg0 + kt * BK;
        const uint32_t Bb = Sb + A_TILE_H * 2;
        #pragma unroll
        for (int r = 0; r < 8; r++) {
            int i   = tid + r * 256;      // 2048 chunks
            int row = i >> 3;
            int cv  = (i & 7) * 8;
            cp_async16_s(Bb + (row * PITCH + cv) * 2, Bg + (size_t)row * KDIM + cv);
        }
    };

    float acc[4][8][4];
    #pragma unroll
    for (int a = 0; a < 4; a++)
        #pragma unroll
        for (int b = 0; b < 8; b++)
            #pragma unroll
            for (int c = 0; c < 4; c++) acc[a][b][c] = 0.0f;

    load_tile(0, 0); cp_commit();
    load_tile(1, 1); cp_commit();
    load_tile(2, 2); cp_commit();

    for (int kt = 0; kt < KT; kt++) {
        // tile kt complete (groups kt+1, kt+2 may stay in flight)
        asm volatile("cp.async.wait_group 2;\n" ::: "memory");
        __syncthreads();   // all warps done reading stage (kt+3)%4 (read at iter kt-1)

        int lt = kt + 3;
        if (lt < KT) load_tile(lt, lt & 3);
        cp_commit();

        const uint32_t Asc = S_u + ((kt & 3) * STAGE_H) * 2;
        const uint32_t Bsc = Asc + A_TILE_H * 2;

        #pragma unroll
        for (int ks = 0; ks < 4; ks++) {
            const int kb = ks * 16;      // halves
            uint32_t af[4][4];
            uint32_t bf[8][2];
            #pragma unroll
            for (int tm = 0; tm < 4; tm++) {
                ldsm_x4(af[tm][0], af[tm][1], af[tm][2], af[tm][3],
                        Asc + (a_off + tm * 16 * PITCH + kb) * 2);
            }
            #pragma unroll
            for (int q = 0; q < 4; q++) {
                ldsm_x4(bf[2 * q][0], bf[2 * q][1], bf[2 * q + 1][0], bf[2 * q + 1][1],
                        Bsc + (b_off + q * 16 * PITCH + kb) * 2);
            }
            #pragma unroll
            for (int tm = 0; tm < 4; tm++) {
                #pragma unroll
                for (int tn = 0; tn < 8; tn++) {
                    asm volatile(
                        "mma.sync.aligned.m16n8k16.row.col.f32.f16.f16.f32 "
                        "{%0,%1,%2,%3}, {%4,%5,%6,%7}, {%8,%9}, {%0,%1,%2,%3};\n"
                        : "+f"(acc[tm][tn][0]), "+f"(acc[tm][tn][1]),
                          "+f"(acc[tm][tn][2]), "+f"(acc[tm][tn][3])
                        : "r"(af[tm][0]), "r"(af[tm][1]), "r"(af[tm][2]), "r"(af[tm][3]),
                          "r"(bf[tn][0]), "r"(bf[tn][1]));
                }
            }
        }
    }

    // ---- epilogue: C(n=m_row, c) -> out[b, n, e],  c = b*64 + e ----
    #pragma unroll
    for (int tm = 0; tm < 4; tm++) {
        #pragma unroll
        for (int tn = 0; tn < 8; tn++) {
            int m0 = bm * BM + wm + tm * 16 + g;
            int c0 = bn * BN + wn + tn * 8 + t4 * 2;
            int bb = c0 >> 6;
            int ee = c0 & 63;
            float2 v0 = make_float2(acc[tm][tn][0], acc[tm][tn][1]);
            float2 v1 = make_float2(acc[tm][tn][2], acc[tm][tn][3]);
            *reinterpret_cast<float2*>(out + ((size_t)(bb * 4096 + m0) * 64 + ee))       = v0;
            *reinterpret_cast<float2*>(out + ((size_t)(bb * 4096 + (m0 + 8)) * 64 + ee)) = v1;
        }
    }
}

// ---------------- launch ----------------
extern "C" void kernel_launch(void* const* d_in, const int* in_sizes, int n_in,
                              void* d_out, int out_size) {
    const float* Z = (const float*)d_in[0];   // [16, 4096, 64]
    const float* A = (const float*)d_in[1];   // [4096, 4096]
    const float* W = (const float*)d_in[2];   // [64, 64]
    float* out = (float*)d_out;               // [16, 4096, 64]
    (void)in_sizes; (void)n_in; (void)out_size;

    cudaFuncSetAttribute(gemm2_kernel,
                         cudaFuncAttributeMaxDynamicSharedMemorySize, SMEM_BYTES);

    convA_kernel<<<16384, 256>>>(reinterpret_cast<const float4*>(A));
    gemm1_kernel<<<dim3(64, 16), 256>>>(Z, W);
    gemm2_kernel<<<dim3(4, 32), 256, SMEM_BYTES>>>(out);
}

// round 12
// speedup vs baseline: 2.1415x; 1.0507x over previous
#include <cuda_runtime.h>
#include <cuda_fp16.h>
#include <cstdint>

// out[b,n,e] = sum_m A[n,m] * (sum_d Z[b,m,d] * W[d,e])
// B=16, N=4096, D_IN=64, D_OUT=64
//   convA: A_h = fp16(A)                          [4096][4096] half, K-major
//   gemm1: Xt[c][m] = fp16(sum_d Z[b,m,d]*W[d,e]) [1024][4096] half, K-major (c=b*64+e)
//   gemm2: split-K makespan-balanced workers -> partials; reduce: out = p0 + p1
//
// Work decomposition: 128 output tiles (32 bm x 4 bn) x 64 k-chunks (BK=64 halves)
// = 8192 units. Worker w in [0,147) owns units [56w, 56w+56). Each tile receives
// exactly 2 contributors (one run covering its window start -> slot0, one run
// starting strictly inside -> slot1); 2-way fp32 add is order-independent.

#define NCOLSX 1024
#define KDIM  4096

__device__ __align__(1024) __half g_Ah[4096 * KDIM];       // fp16 A (32 MB)
__device__ __align__(1024) __half g_Xt[NCOLSX * KDIM];     // fp16 (Z@W)^T (8 MB)
__device__ __align__(1024) float  g_part[2 * 128 * 32768]; // partials (33.5 MB)

// ---------------- helpers ----------------
__device__ __forceinline__ uint32_t smem_u32(const void* p) {
    return (uint32_t)__cvta_generic_to_shared(p);
}
__device__ __forceinline__ void cp_async16_s(uint32_t dst_smem, const void* src) {
    asm volatile("cp.async.cg.shared.global [%0], [%1], 16;\n"
                 :: "r"(dst_smem), "l"(src) : "memory");
}
__device__ __forceinline__ void cp_commit() {
    asm volatile("cp.async.commit_group;\n" ::: "memory");
}
__device__ __forceinline__ void ldsm_x4(uint32_t& r0, uint32_t& r1, uint32_t& r2, uint32_t& r3,
                                        uint32_t addr) {
    asm volatile("ldmatrix.sync.aligned.m8n8.x4.shared.b16 {%0,%1,%2,%3}, [%4];\n"
                 : "=r"(r0), "=r"(r1), "=r"(r2), "=r"(r3) : "r"(addr) : "memory");
}

// ---------------- kernel 0: A -> fp16 ----------------
__global__ void __launch_bounds__(256) convA_kernel(const float4* __restrict__ A) {
    int i = blockIdx.x * 256 + threadIdx.x;   // 16384 * 256 = 4,194,304 float4
    float4 v = __ldg(A + i);
    __half2 h0 = __floats2half2_rn(v.x, v.y);
    __half2 h1 = __floats2half2_rn(v.z, v.w);
    uint2 o;
    o.x = *reinterpret_cast<uint32_t*>(&h0);
    o.y = *reinterpret_cast<uint32_t*>(&h1);
    reinterpret_cast<uint2*>(g_Ah)[i] = o;
}

// ---------------- kernel 1: Xt = fp16((Z @ W)^T) ----------------
__global__ void __launch_bounds__(256) gemm1_kernel(const float* __restrict__ Z,
                                                    const float* __restrict__ W) {
    __shared__ float Zs[64 * 65];
    __shared__ float Ws[64 * 64];
    const int tid = threadIdx.x;
    const int m0  = blockIdx.x * 64;
    const int b   = blockIdx.y;

    const float* Zg = Z + (size_t)((b << 12) + m0) * 64;
    #pragma unroll
    for (int r = 0; r < 4; r++) {
        int i = tid + r * 256;            // 1024 float4
        int row = i >> 4, c4 = (i & 15) * 4;
        float4 v = __ldg(reinterpret_cast<const float4*>(Zg + (size_t)row * 64 + c4));
        float* zp = Zs + row * 65 + c4;
        zp[0] = v.x; zp[1] = v.y; zp[2] = v.z; zp[3] = v.w;
    }
    #pragma unroll
    for (int r = 0; r < 4; r++) {
        int i = tid + r * 256;
        reinterpret_cast<float4*>(Ws)[i] = __ldg(reinterpret_cast<const float4*>(W) + i);
    }
    __syncthreads();

    const int ml = tid & 63;
    const int e0 = (tid >> 6) * 16;

    float acc[16];
    #pragma unroll
    for (int j = 0; j < 16; j++) acc[j] = 0.0f;

    #pragma unroll 4
    for (int d = 0; d < 64; d++) {
        float zv = Zs[ml * 65 + d];
        const float4* wp = reinterpret_cast<const float4*>(Ws + d * 64 + e0);
        #pragma unroll
        for (int q = 0; q < 4; q++) {
            float4 w = wp[q];
            acc[q * 4 + 0] = fmaf(zv, w.x, acc[q * 4 + 0]);
            acc[q * 4 + 1] = fmaf(zv, w.y, acc[q * 4 + 1]);
            acc[q * 4 + 2] = fmaf(zv, w.z, acc[q * 4 + 2]);
            acc[q * 4 + 3] = fmaf(zv, w.w, acc[q * 4 + 3]);
        }
    }

    #pragma unroll
    for (int j = 0; j < 16; j++) {
        g_Xt[(size_t)((b << 6) + e0 + j) * KDIM + m0 + ml] = __float2half_rn(acc[j]);
    }
}

// ---------------- kernel 2: split-K worker (fp16 mma m16n8k16) ----------------
// Tile 128(M) x 256(N), 256 threads / 8 warps (2 along M x 4 along N), warp 64x64.
// BK=64 halves per k-chunk (128 B rows), 4 stages, single sync per chunk.
#define BM 128
#define BN 256
#define BK 64
#define PITCH 72                       // 64 + 8 pad halves (144 B) -> conflict-free ldmatrix
#define A_TILE_H (BM * PITCH)          // 9216 halves
#define B_TILE_H (BN * PITCH)          // 18432 halves
#define STAGE_H  (A_TILE_H + B_TILE_H) // 27648 halves
#define SMEM_BYTES (4 * STAGE_H * 2)   // 221184
#define RUN 56                         // units per worker
#define NUNITS 8192                    // 128 tiles * 64 chunks
#define NWORKERS 147                   // ceil(8192/56)

__global__ void __launch_bounds__(256, 1) gemm2_kernel() {
    extern __shared__ __half smem[];

    const int tid  = threadIdx.x;
    const int wid  = tid >> 5;
    const int lane = tid & 31;
    const int g    = lane >> 2;
    const int t4   = lane & 3;
    const int wm   = (wid & 1) * 64;
    const int wn   = (wid >> 1) * 64;

    const uint32_t S_u = smem_u32(smem);
    const int a_off = (wm + (lane & 15)) * PITCH + (lane >> 4) * 8;
    const int b_off = (wn + ((lane >> 4) << 3) + (lane & 7)) * PITCH + ((lane >> 3) & 1) * 8;

    const int u0 = RUN * blockIdx.x;
    const int u1 = min(u0 + RUN, NUNITS);

    int u = u0;
    while (u < u1) {
        const int t   = u >> 6;                 // tile id
        const int c0  = u & 63;                 // first chunk in tile
        const int len = min(64 - c0, u1 - u);   // >= 8 always
        const int slot = (u0 > (t << 6)) ? 1 : 0;
        const int bm = t >> 2;
        const int bn = t & 3;

        const __half* Ag0 = g_Ah + (size_t)(bm * BM) * KDIM + (size_t)c0 * BK;
        const __half* Bg0 = g_Xt + (size_t)(bn * BN) * KDIM + (size_t)c0 * BK;

        auto load_tile = [&](int i, int s) {
            const uint32_t Sb = S_u + (s * STAGE_H) * 2;
            const __half* Ag = Ag0 + i * BK;
            #pragma unroll
            for (int r = 0; r < 4; r++) {
                int j   = tid + r * 256;
                int row = j >> 3;
                int cv  = (j & 7) * 8;
                cp_async16_s(Sb + (row * PITCH + cv) * 2, Ag + (size_t)row * KDIM + cv);
            }
            const __half* Bg = Bg0 + i * BK;
            const uint32_t Bb = Sb + A_TILE_H * 2;
            #pragma unroll
            for (int r = 0; r < 8; r++) {
                int j   = tid + r * 256;
                int row = j >> 3;
                int cv  = (j & 7) * 8;
                cp_async16_s(Bb + (row * PITCH + cv) * 2, Bg + (size_t)row * KDIM + cv);
            }
        };

        float acc[4][8][4];
        #pragma unroll
        for (int a = 0; a < 4; a++)
            #pragma unroll
            for (int b = 0; b < 8; b++)
                #pragma unroll
                for (int c = 0; c < 4; c++) acc[a][b][c] = 0.0f;

        load_tile(0, 0); cp_commit();
        load_tile(1, 1); cp_commit();
        load_tile(2, 2); cp_commit();

        for (int i = 0; i < len; i++) {
            asm volatile("cp.async.wait_group 2;\n" ::: "memory");
            __syncthreads();

            int li = i + 3;
            if (li < len) load_tile(li, li & 3);
            cp_commit();

            const uint32_t Asc = S_u + ((i & 3) * STAGE_H) * 2;
            const uint32_t Bsc = Asc + A_TILE_H * 2;

            #pragma unroll
            for (int ks = 0; ks < 4; ks++) {
                const int kb = ks * 16;
                uint32_t af[4][4];
                uint32_t bf[8][2];
                #pragma unroll
                for (int tm = 0; tm < 4; tm++) {
                    ldsm_x4(af[tm][0], af[tm][1], af[tm][2], af[tm][3],
                            Asc + (a_off + tm * 16 * PITCH + kb) * 2);
                }
                #pragma unroll
                for (int q = 0; q < 4; q++) {
                    ldsm_x4(bf[2 * q][0], bf[2 * q][1], bf[2 * q + 1][0], bf[2 * q + 1][1],
                            Bsc + (b_off + q * 16 * PITCH + kb) * 2);
                }
                #pragma unroll
                for (int tm = 0; tm < 4; tm++) {
                    #pragma unroll
                    for (int tn = 0; tn < 8; tn++) {
                        asm volatile(
                            "mma.sync.aligned.m16n8k16.row.col.f32.f16.f16.f32 "
                            "{%0,%1,%2,%3}, {%4,%5,%6,%7}, {%8,%9}, {%0,%1,%2,%3};\n"
                            : "+f"(acc[tm][tn][0]), "+f"(acc[tm][tn][1]),
                              "+f"(acc[tm][tn][2]), "+f"(acc[tm][tn][3])
                            : "r"(af[tm][0]), "r"(af[tm][1]), "r"(af[tm][2]), "r"(af[tm][3]),
                              "r"(bf[tn][0]), "r"(bf[tn][1]));
                    }
                }
            }
        }
        __syncthreads();   // all warps done with smem before next segment's prologue

        // partial epilogue -> g_part[slot][t][m_local][n_local]
        float* P = g_part + ((size_t)slot * 128 + t) * 32768;
        #pragma unroll
        for (int tm = 0; tm < 4; tm++) {
            #pragma unroll
            for (int tn = 0; tn < 8; tn++) {
                int ml = wm + tm * 16 + g;
                int cl = wn + tn * 8 + t4 * 2;
                *reinterpret_cast<float2*>(P + ml * 256 + cl) =
                    make_float2(acc[tm][tn][0], acc[tm][tn][1]);
                *reinterpret_cast<float2*>(P + (ml + 8) * 256 + cl) =
                    make_float2(acc[tm][tn][2], acc[tm][tn][3]);
            }
        }

        u += len;
    }
}

// ---------------- kernel 3: out = part0 + part1 ----------------
// out has 16*4096*64 = 4,194,304 floats = 1,048,576 float4 -> grid 4096 x 256.
__global__ void __launch_bounds__(256) reduce_kernel(float4* __restrict__ out) {
    int j  = blockIdx.x * 256 + threadIdx.x;   // float4 id, 1,048,576 total
    int e4 = j & 15;                           // 16 float4 per 64-e row
    int r  = j >> 4;                           // bb*4096 + n   (65,536 rows)
    int bb = r >> 12;
    int n  = r & 4095;
    int c0 = bb * 64 + e4 * 4;                 // column id in [0,1024)
    int t  = ((n >> 7) << 2) + (c0 >> 8);      // tile id
    int p  = t * 32768 + (n & 127) * 256 + (c0 & 255);
    float4 a = __ldg(reinterpret_cast<const float4*>(g_part + p));
    float4 b = __ldg(reinterpret_cast<const float4*>(g_part + 128 * 32768 + p));
    out[j] = make_float4(a.x + b.x, a.y + b.y, a.z + b.z, a.w + b.w);
}

// ---------------- launch ----------------
extern "C" void kernel_launch(void* const* d_in, const int* in_sizes, int n_in,
                              void* d_out, int out_size) {
    const float* Z = (const float*)d_in[0];   // [16, 4096, 64]
    const float* A = (const float*)d_in[1];   // [4096, 4096]
    const float* W = (const float*)d_in[2];   // [64, 64]
    float* out = (float*)d_out;               // [16, 4096, 64]
    (void)in_sizes; (void)n_in; (void)out_size;

    // One-time resource setup (no device-memory allocation involved).
    static cudaStream_t s2 = nullptr;
    static cudaEvent_t evF = nullptr, evJ = nullptr;
    if (!s2) {
        cudaStreamCreateWithFlags(&s2, cudaStreamNonBlocking);
        cudaEventCreateWithFlags(&evF, cudaEventDisableTiming);
        cudaEventCreateWithFlags(&evJ, cudaEventDisableTiming);
        cudaFuncSetAttribute(gemm2_kernel,
                             cudaFuncAttributeMaxDynamicSharedMemorySize, SMEM_BYTES);
    }

    // Fork gemm1 (independent of convA) onto the side stream; join before gemm2.
    cudaEventRecord(evF, 0);
    cudaStreamWaitEvent(s2, evF, 0);

    gemm1_kernel<<<dim3(64, 16), 256, 0, s2>>>(Z, W);
    cudaEventRecord(evJ, s2);

    convA_kernel<<<16384, 256>>>(reinterpret_cast<const float4*>(A));

    cudaStreamWaitEvent(0, evJ, 0);
    gemm2_kernel<<<NWORKERS, 256, SMEM_BYTES>>>();
    reduce_kernel<<<4096, 256>>>(reinterpret_cast<float4*>(out));
}